// round 3
// baseline (speedup 1.0000x reference)
#include <cuda_runtime.h>

#define BB 64
#define SS 512
#define EE 512
#define AA 256
#define HP 256
#define PP 128
#define DD 1024
#define MM 128
#define TT 800
#define G3 3072
#define NB 128
#define TPB 512

// ---------------- static scratch ----------------
__device__ __align__(128) float g_ep  [BB*SS*AA];
__device__ __align__(128) float g_prev[TT*BB*MM];
__device__ __align__(128) float g_ph  [TT*BB*HP];
__device__ __align__(128) float g_pre [TT*BB*PP];
__device__ __align__(128) float g_h   [BB*DD];
__device__ __align__(128) float g_ctx [BB*EE];
__device__ __align__(128) float g_sc  [BB*SS];
__device__ __align__(128) float g_g   [4*BB*G3];
__device__ __align__(128) float g_dpp [NB*BB*AA];          // 8MB: 128 kparts x 64 b x 256 a
__device__ __align__(128) float g_Hb  [(size_t)TT*BB*DD];
__device__ __align__(128) float g_Cb  [(size_t)TT*BB*EE];
__device__ unsigned g_cnt;
__device__ unsigned g_gen;

__device__ __forceinline__ float fsig(float x){
    float e = __expf(-x);
    return __fdividef(1.f, 1.f + e);
}
__device__ __forceinline__ float ftanh(float x){
    x = fminf(fmaxf(x, -15.f), 15.f);
    float e = __expf(2.f*x);
    return __fdividef(e - 1.f, e + 1.f);
}

// grid barrier: generation counter; self-restoring across launches/replays
__device__ __forceinline__ void gsync(){
    __syncthreads();
    if (threadIdx.x == 0){
        unsigned gen = *((volatile unsigned*)&g_gen);
        __threadfence();                       // drain writes; CCTL.IVALL
        if (atomicAdd(&g_cnt, 1u) == NB - 1u){
            atomicExch(&g_cnt, 0u);
            __threadfence();
            atomicAdd(&g_gen, 1u);
        } else {
            while (*((volatile unsigned*)&g_gen) == gen) __nanosleep(64);
        }
        __threadfence();                       // acquire: invalidate L1
    }
    __syncthreads();
}

// ---------------- generic tiled SGEMM (pre/epilogue only) ----------------
#define BKK 16
__global__ void sgemm(const float* __restrict__ A, const float* __restrict__ B,
                      const float* __restrict__ bias, float* __restrict__ C,
                      int M, int N, int K, int flags, int Bdim, int Tdim)
{
    __shared__ float As[BKK][64];
    __shared__ float Bs[BKK][64];
    const int n0 = blockIdx.x * 64;
    const int m0 = blockIdx.y * 64;
    const int tid = threadIdx.x;
    const int tx = tid & 15;
    const int ty = tid >> 4;
    float acc[4][4] = {};
    const int arow  = tid >> 2;
    const int acol4 = (tid & 3) * 4;
    const int brow  = tid >> 4;
    const int bcol4 = (tid & 15) * 4;

    for (int k = 0; k < K; k += BKK) {
        float4 av = *(const float4*)(A + (size_t)(m0 + arow) * K + k + acol4);
        As[acol4+0][arow] = av.x;
        As[acol4+1][arow] = av.y;
        As[acol4+2][arow] = av.z;
        As[acol4+3][arow] = av.w;
        float4 bvv = *(const float4*)(B + (size_t)(k + brow) * N + n0 + bcol4);
        *(float4*)(&Bs[brow][bcol4]) = bvv;
        __syncthreads();
        #pragma unroll
        for (int kk = 0; kk < BKK; kk++) {
            float4 a4 = *(const float4*)(&As[kk][ty*4]);
            float4 b4 = *(const float4*)(&Bs[kk][tx*4]);
            acc[0][0] += a4.x*b4.x; acc[0][1] += a4.x*b4.y; acc[0][2] += a4.x*b4.z; acc[0][3] += a4.x*b4.w;
            acc[1][0] += a4.y*b4.x; acc[1][1] += a4.y*b4.y; acc[1][2] += a4.y*b4.z; acc[1][3] += a4.y*b4.w;
            acc[2][0] += a4.z*b4.x; acc[2][1] += a4.z*b4.y; acc[2][2] += a4.z*b4.z; acc[2][3] += a4.z*b4.w;
            acc[3][0] += a4.w*b4.x; acc[3][1] += a4.w*b4.y; acc[3][2] += a4.w*b4.z; acc[3][3] += a4.w*b4.w;
        }
        __syncthreads();
    }
    #pragma unroll
    for (int i = 0; i < 4; i++) {
        const int m = m0 + ty*4 + i;
        #pragma unroll
        for (int j = 0; j < 4; j++) {
            const int n = n0 + tx*4 + j;
            float val = acc[i][j];
            if (bias) val += bias[n];
            if (flags & 1) val = fmaxf(val, 0.f);
            size_t idx;
            if (Bdim > 0) {
                const int bq = m % Bdim, tq = m / Bdim;
                idx = ((size_t)bq * Tdim + tq) * N + n;
            } else {
                idx = (size_t)m * N + n;
            }
            if (flags & 2) C[idx] += val; else C[idx] = val;
        }
    }
}

__global__ void k_init(){
    int i = blockIdx.x*256 + threadIdx.x;
    if (i < NB*BB*AA) g_dpp[i] = 0.f;
    if (i < BB*DD)    g_h[i]   = 0.f;
}

__global__ void k_prev(const float* __restrict__ tm){
    int i = blockIdx.x*256 + threadIdx.x;
    if (i >= TT*BB*MM) return;
    int m  = i & (MM-1);
    int tb = i >> 7;
    int b  = tb & (BB-1);
    int t  = tb >> 6;
    g_prev[i] = (t == 0) ? 0.f : tm[((size_t)b*TT + (t-1))*MM + m];
}

__global__ void k_stop(const float* __restrict__ Ws, const float* __restrict__ bs,
                       float* __restrict__ dout){
    const int w = (blockIdx.x*blockDim.x + threadIdx.x) >> 5;
    const int lane = threadIdx.x & 31;
    if (w >= TT*BB) return;
    const float* hrow = g_Hb + (size_t)w*DD;
    const float* crow = g_Cb + (size_t)w*EE;
    float acc = 0.f;
    for (int k = lane; k < DD; k += 32) acc += hrow[k]*Ws[k];
    for (int k = lane; k < EE; k += 32) acc += crow[k]*Ws[DD+k];
    #pragma unroll
    for (int o = 16; o > 0; o >>= 1) acc += __shfl_down_sync(0xffffffffu, acc, o);
    if (lane == 0){
        const int tq = w / BB, bq = w % BB;
        dout[(size_t)BB*TT*MM + (size_t)bq*TT + tq] = acc + bs[0];
    }
}

// ================= persistent decode kernel =================
__global__ void __launch_bounds__(TPB)
decode(const float* __restrict__ enc, const float* __restrict__ Wd,
       const float* __restrict__ bd,  const float* __restrict__ v,
       const float* __restrict__ bv,  const float* __restrict__ Wih,
       const float* __restrict__ bih, const float* __restrict__ Whh,
       const float* __restrict__ bhh, float* __restrict__ out)
{
    __shared__ float sm[5504];
    const int blk = blockIdx.x, tid = threadIdx.x;

    for (int t = 0; t < TT; t++){
        // ---------- A: dp partial-sum + attention scores ----------
        {
            const int b = blk >> 1, sh = blk & 1;
            float* dps = sm; float* vs = sm + AA;
            if (tid < AA){
                float s = bd[tid];
                const float* pp = g_dpp + (size_t)b*AA + tid;
                #pragma unroll 8
                for (int j = 0; j < NB; j++) s += pp[(size_t)j*BB*AA];
                dps[tid] = s; vs[tid] = v[tid];
            }
            __syncthreads();
            const int sl = tid >> 1, ah = tid & 1;
            const int s = sh*256 + sl;
            const float4* ep4 = (const float4*)(g_ep + ((size_t)(b*SS + s))*AA + ah*128);
            const float* dp2 = dps + ah*128;
            const float* v2  = vs  + ah*128;
            float acc = 0.f;
            #pragma unroll 8
            for (int q = 0; q < 32; q++){
                float4 e = ep4[q];
                acc += v2[q*4+0]*ftanh(e.x + dp2[q*4+0]);
                acc += v2[q*4+1]*ftanh(e.y + dp2[q*4+1]);
                acc += v2[q*4+2]*ftanh(e.z + dp2[q*4+2]);
                acc += v2[q*4+3]*ftanh(e.w + dp2[q*4+3]);
            }
            acc += __shfl_xor_sync(0xffffffffu, acc, 1);
            if (ah == 0) g_sc[b*SS + s] = acc + bv[0];
            __syncthreads();
        }
        gsync();
        // ---------- B: softmax + context ----------
        {
            const int b = blk >> 1, eh = blk & 1;
            float* aw = sm; float* red = sm + SS;
            float sc = g_sc[b*SS + tid];
            red[tid] = sc; __syncthreads();
            #pragma unroll
            for (int o = 256; o > 0; o >>= 1){ if (tid < o) red[tid] = fmaxf(red[tid], red[tid+o]); __syncthreads(); }
            const float mx = red[0]; __syncthreads();
            float ev = __expf(sc - mx);
            red[tid] = ev; __syncthreads();
            #pragma unroll
            for (int o = 256; o > 0; o >>= 1){ if (tid < o) red[tid] += red[tid+o]; __syncthreads(); }
            const float inv = __fdividef(1.f, red[0]); __syncthreads();
            float a = ev * inv;
            aw[tid] = a;
            if (eh == 0)
                out[(size_t)BB*TT*MM + (size_t)BB*TT + ((size_t)b*TT + t)*SS + tid] = a;
            __syncthreads();
            const int el = tid & 255, shalf = tid >> 8;
            const int e = eh*256 + el;
            const float* eb = enc + ((size_t)b*SS + shalf*256)*EE + e;
            float c = 0.f;
            #pragma unroll 4
            for (int s2 = 0; s2 < 256; s2++) c += aw[shalf*256 + s2]*eb[(size_t)s2*EE];
            red[tid] = c; __syncthreads();
            if (tid < 256){
                float cc = red[tid] + red[tid+256];
                const int e2 = eh*256 + tid;
                g_ctx[b*EE + e2] = cc;
                g_Cb[((size_t)t*BB + b)*EE + e2] = cc;
            }
            __syncthreads();
        }
        gsync();
        // ---------- C: gates GEMM (k-split x4 into g_g partials) ----------
        {
            const int p = blk >> 5, c = blk & 31;
            const int n0 = c * 96;
            const int kbase = (p==0)?0 : (p==1)?320 : (p==2)?0 : 512;
            const int klen  = (p<2)?320:512;
            const bool isx = (p < 2);
            const float* Bsrc = (isx ? Wih : Whh) + (size_t)kbase*G3 + n0;
            float* As = sm;            // 64*36
            float* Bs = sm + 2304;     // 32*100
            float acc[4][3] = {};
            const int rowb = tid >> 3, k4 = (tid & 7)*4;
            const int ty = tid >> 5,  tx = tid & 31;
            const int brow1 = tid/24,        bc1 = (tid%24)*4;
            const int brow2 = (tid+512)/24,  bc2 = ((tid+512)%24)*4;
            const bool act2 = (tid + 512) < 768;
            for (int kc = 0; kc < klen; kc += 32){
                float4 av;
                const int col = kbase + kc + k4;
                if (isx){
                    if (col < PP) av = *(const float4*)(g_pre + ((size_t)(t*BB + rowb))*PP + col);
                    else          av = *(const float4*)(g_ctx + (size_t)rowb*EE + (col - PP));
                } else {
                    av = *(const float4*)(g_h + (size_t)rowb*DD + col);
                }
                *(float4*)(As + rowb*36 + k4) = av;
                *(float4*)(Bs + brow1*100 + bc1) = *(const float4*)(Bsrc + (size_t)(kc + brow1)*G3 + bc1);
                if (act2)
                    *(float4*)(Bs + brow2*100 + bc2) = *(const float4*)(Bsrc + (size_t)(kc + brow2)*G3 + bc2);
                __syncthreads();
                #pragma unroll
                for (int kk = 0; kk < 32; kk++){
                    const float a0 = As[(ty*4+0)*36 + kk];
                    const float a1 = As[(ty*4+1)*36 + kk];
                    const float a2 = As[(ty*4+2)*36 + kk];
                    const float a3 = As[(ty*4+3)*36 + kk];
                    const float b0 = Bs[kk*100 + tx*3 + 0];
                    const float b1 = Bs[kk*100 + tx*3 + 1];
                    const float b2 = Bs[kk*100 + tx*3 + 2];
                    acc[0][0]+=a0*b0; acc[0][1]+=a0*b1; acc[0][2]+=a0*b2;
                    acc[1][0]+=a1*b0; acc[1][1]+=a1*b1; acc[1][2]+=a1*b2;
                    acc[2][0]+=a2*b0; acc[2][1]+=a2*b1; acc[2][2]+=a2*b2;
                    acc[3][0]+=a3*b0; acc[3][1]+=a3*b1; acc[3][2]+=a3*b2;
                }
                __syncthreads();
            }
            float* gout = g_g + (size_t)p*BB*G3;
            #pragma unroll
            for (int i = 0; i < 4; i++)
                #pragma unroll
                for (int j = 0; j < 3; j++)
                    gout[(size_t)(ty*4+i)*G3 + n0 + tx*3 + j] = acc[i][j];
        }
        gsync();
        // ---------- D: GRU pointwise + dec_proj k-partials for t+1 ----------
        {
            const int d0 = blk * 8;
            float* Wds = sm;          // 8*256
            float* hs  = sm + 2048;   // 64*8
            {
                const int row = tid >> 6, c4 = (tid & 63)*4;
                *(float4*)(Wds + row*256 + c4) = *(const float4*)(Wd + (size_t)(d0+row)*AA + c4);
            }
            {
                const int b = tid >> 3, dl = tid & 7, d = d0 + dl;
                const size_t base = (size_t)b*G3;
                float gr  = bih[d] + bhh[d];
                float gz  = bih[DD + d] + bhh[DD + d];
                float gin = bih[2*DD + d];
                float ghn = bhh[2*DD + d];
                #pragma unroll
                for (int pq = 0; pq < 4; pq++){
                    const float* gp = g_g + (size_t)pq*BB*G3 + base;
                    gr += gp[d]; gz += gp[DD + d];
                    if (pq < 2) gin += gp[2*DD + d]; else ghn += gp[2*DD + d];
                }
                const float r = fsig(gr), z = fsig(gz);
                const float n = ftanh(gin + r*ghn);
                const float h = g_h[(size_t)b*DD + d];
                const float hn = (1.f - z)*n + z*h;
                g_h[(size_t)b*DD + d] = hn;
                g_Hb[((size_t)t*BB + b)*DD + d] = hn;
                hs[b*8 + dl] = hn;
            }
            __syncthreads();
            {
                const int bg = tid >> 5, ag = tid & 31;
                const int b4 = bg*4, a8 = ag*8;
                float acc[4][8] = {};
                #pragma unroll
                for (int kk = 0; kk < 8; kk++){
                    const float4 w0 = *(const float4*)(Wds + kk*256 + a8);
                    const float4 w1 = *(const float4*)(Wds + kk*256 + a8 + 4);
                    #pragma unroll
                    for (int i = 0; i < 4; i++){
                        const float h = hs[(b4+i)*8 + kk];
                        acc[i][0]+=h*w0.x; acc[i][1]+=h*w0.y; acc[i][2]+=h*w0.z; acc[i][3]+=h*w0.w;
                        acc[i][4]+=h*w1.x; acc[i][5]+=h*w1.y; acc[i][6]+=h*w1.z; acc[i][7]+=h*w1.w;
                    }
                }
                #pragma unroll
                for (int i = 0; i < 4; i++){
                    float* o = g_dpp + ((size_t)blk*BB + b4 + i)*AA + a8;
                    *(float4*)(o)   = make_float4(acc[i][0],acc[i][1],acc[i][2],acc[i][3]);
                    *(float4*)(o+4) = make_float4(acc[i][4],acc[i][5],acc[i][6],acc[i][7]);
                }
            }
        }
        gsync();
    }
}

// ---------------- host ----------------
extern "C" void kernel_launch(void* const* d_in, const int* in_sizes, int n_in,
                              void* d_out, int out_size){
    const float* enc = (const float*)d_in[0];
    const float* tm  = (const float*)d_in[1];
    const float* We  = (const float*)d_in[2];
    const float* be  = (const float*)d_in[3];
    const float* Wd  = (const float*)d_in[4];
    const float* bd  = (const float*)d_in[5];
    const float* v   = (const float*)d_in[6];
    const float* bv  = (const float*)d_in[7];
    const float* W1  = (const float*)d_in[8];
    const float* b1  = (const float*)d_in[9];
    const float* W2  = (const float*)d_in[10];
    const float* b2  = (const float*)d_in[11];
    const float* Wih = (const float*)d_in[12];
    const float* bih = (const float*)d_in[13];
    const float* Whh = (const float*)d_in[14];
    const float* bhh = (const float*)d_in[15];
    const float* Wo  = (const float*)d_in[16];
    const float* bo  = (const float*)d_in[17];
    const float* Ws  = (const float*)d_in[18];
    const float* bs  = (const float*)d_in[19];
    float* out = (float*)d_out;

    float *p_ep, *p_prev, *p_ph, *p_pre, *p_Hb, *p_Cb;
    cudaGetSymbolAddress((void**)&p_ep,   g_ep);
    cudaGetSymbolAddress((void**)&p_prev, g_prev);
    cudaGetSymbolAddress((void**)&p_ph,   g_ph);
    cudaGetSymbolAddress((void**)&p_pre,  g_pre);
    cudaGetSymbolAddress((void**)&p_Hb,   g_Hb);
    cudaGetSymbolAddress((void**)&p_Cb,   g_Cb);

    // precompute
    k_init<<<(NB*BB*AA + 255)/256, 256>>>();
    k_prev<<<(TT*BB*MM + 255)/256, 256>>>(tm);
    sgemm<<<dim3(HP/64, (TT*BB)/64), 256>>>(p_prev, W1, b1, p_ph,  TT*BB, HP, MM, 1, 0, 0);
    sgemm<<<dim3(PP/64, (TT*BB)/64), 256>>>(p_ph,   W2, b2, p_pre, TT*BB, PP, HP, 1, 0, 0);
    sgemm<<<dim3(AA/64, (BB*SS)/64), 256>>>(enc,    We, be, p_ep,  BB*SS, AA, EE, 0, 0, 0);

    // sequential decode: one persistent kernel
    decode<<<NB, TPB>>>(enc, Wd, bd, v, bv, Wih, bih, Whh, bhh, out);

    // output heads
    sgemm<<<dim3(MM/64, (TT*BB)/64), 256>>>(p_Hb, Wo,           bo,      out, TT*BB, MM, DD, 0, BB, TT);
    sgemm<<<dim3(MM/64, (TT*BB)/64), 256>>>(p_Cb, Wo + DD*MM,   nullptr, out, TT*BB, MM, EE, 2, BB, TT);
    k_stop<<<(TT*BB)/8, 256>>>(Ws, bs, out);
}

// round 4
// speedup vs baseline: 1.0816x; 1.0816x over previous
#include <cuda_runtime.h>
#include <cuda_bf16.h>

#define BB 64
#define SS 512
#define EE 512
#define AA 256
#define HP 256
#define PP 128
#define DD 1024
#define MM 128
#define TT 800
#define G3 3072
#define NB 128
#define TPB 512
#define KTOT 1664
#define NKT 104
#define NCH 26

// ---------------- static scratch ----------------
__device__ __align__(128) float g_ep  [BB*SS*AA];
__device__ __align__(128) float g_prev[TT*BB*MM];
__device__ __align__(128) float g_ph  [TT*BB*HP];
__device__ __align__(128) float g_pre [TT*BB*PP];
__device__ __align__(128) float g_h   [BB*DD];
__device__ __align__(128) float g_sc  [BB*SS];
__device__ __align__(128) float g_dpp [NB*BB*AA];
__device__ __align__(128) __nv_bfloat16 g_Ah[BB*KTOT];
__device__ __align__(128) __nv_bfloat16 g_Al[BB*KTOT];
__device__ __align__(128) uint2 g_Wf[(size_t)NB*NKT*3*2*32];   // 20.4MB frag-packed weights
__device__ __align__(128) float g_Hb  [(size_t)TT*BB*DD];
__device__ __align__(128) float g_Cb  [(size_t)TT*BB*EE];
__device__ unsigned g_cnt, g_gen;

__device__ __forceinline__ float fsig(float x){
    float e = __expf(-x);
    return __fdividef(1.f, 1.f + e);
}
__device__ __forceinline__ float ftanh(float x){
    x = fminf(fmaxf(x, -15.f), 15.f);
    float e = __expf(2.f*x);
    return __fdividef(e - 1.f, e + 1.f);
}

__device__ __forceinline__ void gsync(){
    __syncthreads();
    if (threadIdx.x == 0){
        unsigned gen = *((volatile unsigned*)&g_gen);
        __threadfence();
        if (atomicAdd(&g_cnt, 1u) == NB - 1u){
            atomicExch(&g_cnt, 0u);
            __threadfence();
            atomicAdd(&g_gen, 1u);
        } else {
            while (*((volatile unsigned*)&g_gen) == gen) __nanosleep(64);
        }
        __threadfence();
    }
    __syncthreads();
}

#define MMA(D0,D1,D2,D3,A0,A1,A2,A3,B0,B1) \
    asm volatile("mma.sync.aligned.m16n8k16.row.col.f32.bf16.bf16.f32 " \
        "{%0,%1,%2,%3},{%4,%5,%6,%7},{%8,%9},{%0,%1,%2,%3};" \
        : "+f"(D0),"+f"(D1),"+f"(D2),"+f"(D3) \
        : "r"(A0),"r"(A1),"r"(A2),"r"(A3),"r"(B0),"r"(B1))

// ---------------- generic tiled SGEMM (pre/epilogue only) ----------------
#define BKK 16
__global__ void sgemm(const float* __restrict__ A, const float* __restrict__ B,
                      const float* __restrict__ bias, float* __restrict__ C,
                      int M, int N, int K, int flags, int Bdim, int Tdim)
{
    __shared__ float As[BKK][64];
    __shared__ float Bs[BKK][64];
    const int n0 = blockIdx.x * 64;
    const int m0 = blockIdx.y * 64;
    const int tid = threadIdx.x;
    const int tx = tid & 15;
    const int ty = tid >> 4;
    float acc[4][4] = {};
    const int arow  = tid >> 2;
    const int acol4 = (tid & 3) * 4;
    const int brow  = tid >> 4;
    const int bcol4 = (tid & 15) * 4;

    for (int k = 0; k < K; k += BKK) {
        float4 av = *(const float4*)(A + (size_t)(m0 + arow) * K + k + acol4);
        As[acol4+0][arow] = av.x;
        As[acol4+1][arow] = av.y;
        As[acol4+2][arow] = av.z;
        As[acol4+3][arow] = av.w;
        float4 bvv = *(const float4*)(B + (size_t)(k + brow) * N + n0 + bcol4);
        *(float4*)(&Bs[brow][bcol4]) = bvv;
        __syncthreads();
        #pragma unroll
        for (int kk = 0; kk < BKK; kk++) {
            float4 a4 = *(const float4*)(&As[kk][ty*4]);
            float4 b4 = *(const float4*)(&Bs[kk][tx*4]);
            acc[0][0] += a4.x*b4.x; acc[0][1] += a4.x*b4.y; acc[0][2] += a4.x*b4.z; acc[0][3] += a4.x*b4.w;
            acc[1][0] += a4.y*b4.x; acc[1][1] += a4.y*b4.y; acc[1][2] += a4.y*b4.z; acc[1][3] += a4.y*b4.w;
            acc[2][0] += a4.z*b4.x; acc[2][1] += a4.z*b4.y; acc[2][2] += a4.z*b4.z; acc[2][3] += a4.z*b4.w;
            acc[3][0] += a4.w*b4.x; acc[3][1] += a4.w*b4.y; acc[3][2] += a4.w*b4.z; acc[3][3] += a4.w*b4.w;
        }
        __syncthreads();
    }
    #pragma unroll
    for (int i = 0; i < 4; i++) {
        const int m = m0 + ty*4 + i;
        #pragma unroll
        for (int j = 0; j < 4; j++) {
            const int n = n0 + tx*4 + j;
            float val = acc[i][j];
            if (bias) val += bias[n];
            if (flags & 1) val = fmaxf(val, 0.f);
            size_t idx;
            if (Bdim > 0) {
                const int bq = m % Bdim, tq = m / Bdim;
                idx = ((size_t)bq * Tdim + tq) * N + n;
            } else {
                idx = (size_t)m * N + n;
            }
            if (flags & 2) C[idx] += val; else C[idx] = val;
        }
    }
}

__global__ void k_init(){
    int i = blockIdx.x*256 + threadIdx.x;
    if (i < NB*BB*AA) g_dpp[i] = 0.f;
    if (i < BB*KTOT){ g_Ah[i] = __float2bfloat16(0.f); g_Al[i] = __float2bfloat16(0.f); }
    if (i < BB*DD) g_h[i] = 0.f;
}

__global__ void k_prev(const float* __restrict__ tm){
    int i = blockIdx.x*256 + threadIdx.x;
    if (i >= TT*BB*MM) return;
    int m  = i & (MM-1);
    int tb = i >> 7;
    int b  = tb & (BB-1);
    int t  = tb >> 6;
    g_prev[i] = (t == 0) ? 0.f : tm[((size_t)b*TT + (t-1))*MM + m];
}

// pack [Wih; Whh] (K=1664 x N=3072) into mma B-fragment layout, bf16 hi/lo
__global__ void k_pack(const float* __restrict__ Wih, const float* __restrict__ Whh){
    int id = blockIdx.x*256 + threadIdx.x;
    const int TOTW = NB*NKT*3*32;
    if (id >= TOTW) return;
    int lane = id & 31; int r = id >> 5;
    int nt = r % 3; r /= 3;
    int kt = r % NKT; int blk = r / NKT;
    int g = lane >> 2, tig = lane & 3;
    int n = nt*DD + blk*8 + g;
    int k0 = kt*16;
    int kk[4] = {k0+2*tig, k0+2*tig+1, k0+8+2*tig, k0+9+2*tig};
    unsigned hh[4], ll[4];
    #pragma unroll
    for (int i=0;i<4;i++){
        int k = kk[i];
        float w = (k < PP+EE) ? Wih[(size_t)k*G3 + n] : Whh[(size_t)(k-(PP+EE))*G3 + n];
        __nv_bfloat16 hb = __float2bfloat16(w);
        __nv_bfloat16 lb = __float2bfloat16(w - __bfloat162float(hb));
        hh[i] = *(unsigned short*)&hb;
        ll[i] = *(unsigned short*)&lb;
    }
    size_t base = ((((size_t)blk*NKT + kt)*3 + nt)*2)*32 + lane;
    g_Wf[base]      = make_uint2((hh[1]<<16)|hh[0], (hh[3]<<16)|hh[2]);
    g_Wf[base + 32] = make_uint2((ll[1]<<16)|ll[0], (ll[3]<<16)|ll[2]);
}

__global__ void k_stop(const float* __restrict__ Ws, const float* __restrict__ bs,
                       float* __restrict__ dout){
    const int w = (blockIdx.x*blockDim.x + threadIdx.x) >> 5;
    const int lane = threadIdx.x & 31;
    if (w >= TT*BB) return;
    const float* hrow = g_Hb + (size_t)w*DD;
    const float* crow = g_Cb + (size_t)w*EE;
    float acc = 0.f;
    for (int k = lane; k < DD; k += 32) acc += hrow[k]*Ws[k];
    for (int k = lane; k < EE; k += 32) acc += crow[k]*Ws[DD+k];
    #pragma unroll
    for (int o = 16; o > 0; o >>= 1) acc += __shfl_down_sync(0xffffffffu, acc, o);
    if (lane == 0){
        const int tq = w / BB, bq = w % BB;
        dout[(size_t)BB*TT*MM + (size_t)bq*TT + tq] = acc + bs[0];
    }
}

// ================= persistent decode kernel =================
__global__ void __launch_bounds__(TPB)
decode(const float* __restrict__ enc, const float* __restrict__ Wd,
       const float* __restrict__ bd,  const float* __restrict__ v,
       const float* __restrict__ bv,  const float* __restrict__ bih,
       const float* __restrict__ bhh, float* __restrict__ out)
{
    __shared__ float sm[9216];     // 36KB: 2 x (A-chunk hi 2304 + lo 2304) floats
    const int blk = blockIdx.x, tid = threadIdx.x;

    for (int t = 0; t < TT; t++){
        // ---------- A: dp partial-sum + attention scores (+ pre bf16 staging) ----------
        {
            const int b = blk >> 1, sh = blk & 1;
            float* dps = sm; float* vs = sm + AA;
            if (tid < AA){
                float s = bd[tid];
                const float* pp = g_dpp + (size_t)b*AA + tid;
                #pragma unroll 8
                for (int j = 0; j < NB; j++) s += pp[(size_t)j*BB*AA];
                dps[tid] = s; vs[tid] = v[tid];
            }
            if (sh == 0 && tid >= AA && tid < AA + PP){
                int m = tid - AA;
                float pv = g_pre[((size_t)t*BB + b)*PP + m];
                __nv_bfloat16 hb = __float2bfloat16(pv);
                g_Ah[b*KTOT + m] = hb;
                g_Al[b*KTOT + m] = __float2bfloat16(pv - __bfloat162float(hb));
            }
            __syncthreads();
            const int sl = tid >> 1, ah = tid & 1;
            const int s = sh*256 + sl;
            const float4* ep4 = (const float4*)(g_ep + ((size_t)(b*SS + s))*AA + ah*128);
            const float* dp2 = dps + ah*128;
            const float* v2  = vs  + ah*128;
            float acc = 0.f;
            #pragma unroll 8
            for (int q = 0; q < 32; q++){
                float4 e = ep4[q];
                acc += v2[q*4+0]*ftanh(e.x + dp2[q*4+0]);
                acc += v2[q*4+1]*ftanh(e.y + dp2[q*4+1]);
                acc += v2[q*4+2]*ftanh(e.z + dp2[q*4+2]);
                acc += v2[q*4+3]*ftanh(e.w + dp2[q*4+3]);
            }
            acc += __shfl_xor_sync(0xffffffffu, acc, 1);
            if (ah == 0) g_sc[b*SS + s] = acc + bv[0];
            __syncthreads();
        }
        gsync();
        // ---------- B: softmax + context (+ ctx bf16 staging) ----------
        {
            const int b = blk >> 1, eh = blk & 1;
            float* aw = sm; float* red = sm + SS;
            float sc = g_sc[b*SS + tid];
            red[tid] = sc; __syncthreads();
            #pragma unroll
            for (int o = 256; o > 0; o >>= 1){ if (tid < o) red[tid] = fmaxf(red[tid], red[tid+o]); __syncthreads(); }
            const float mx = red[0]; __syncthreads();
            float ev = __expf(sc - mx);
            red[tid] = ev; __syncthreads();
            #pragma unroll
            for (int o = 256; o > 0; o >>= 1){ if (tid < o) red[tid] += red[tid+o]; __syncthreads(); }
            const float inv = __fdividef(1.f, red[0]); __syncthreads();
            float a = ev * inv;
            aw[tid] = a;
            if (eh == 0)
                out[(size_t)BB*TT*MM + (size_t)BB*TT + ((size_t)b*TT + t)*SS + tid] = a;
            __syncthreads();
            const int el = tid & 255, shalf = tid >> 8;
            const int e = eh*256 + el;
            const float* eb = enc + ((size_t)b*SS + shalf*256)*EE + e;
            float c = 0.f;
            #pragma unroll 4
            for (int s2 = 0; s2 < 256; s2++) c += aw[shalf*256 + s2]*eb[(size_t)s2*EE];
            red[tid] = c; __syncthreads();
            if (tid < 256){
                float cc = red[tid] + red[tid+256];
                const int e2 = eh*256 + tid;
                g_Cb[((size_t)t*BB + b)*EE + e2] = cc;
                __nv_bfloat16 hb = __float2bfloat16(cc);
                g_Ah[b*KTOT + PP + e2] = hb;
                g_Al[b*KTOT + PP + e2] = __float2bfloat16(cc - __bfloat162float(hb));
            }
            __syncthreads();
        }
        gsync();
        // ---------- C: gates mma GEMM + GRU + dp partials ----------
        {
            const int w = tid >> 5, lane = tid & 31;
            const int g = lane >> 2, tig = lane & 3;
            const int nt = w >> 2;             // valid for w<12
            const int m0 = (w & 3) * 16;
            float aX0=0,aX1=0,aX2=0,aX3=0, aH0=0,aH1=0,aH2=0,aH3=0;
            uint2 bh[4], bl[4];
            const int srow = tid >> 3, sc4 = tid & 7;
            unsigned* smu = (unsigned*)sm;
            // preload chunk 0 (A via smem buf0, B frags to regs)
            {
                uint4 vh = ((const uint4*)g_Ah)[srow*208 + sc4];
                uint4 vl = ((const uint4*)g_Al)[srow*208 + sc4];
                ((uint4*)smu)[srow*9 + sc4] = vh;
                ((uint4*)(smu + 2304))[srow*9 + sc4] = vl;
                if (w < 12){
                    size_t wb = (((size_t)blk*NKT*3 + nt)*2)*32 + lane;
                    #pragma unroll
                    for (int kl=0; kl<4; kl++){
                        bh[kl] = g_Wf[wb + (size_t)kl*192];
                        bl[kl] = g_Wf[wb + (size_t)kl*192 + 32];
                    }
                }
            }
            __syncthreads();
            for (int c = 0; c < NCH; c++){
                uint4 nvh, nvl;
                if (c+1 < NCH){
                    nvh = ((const uint4*)g_Ah)[srow*208 + (c+1)*8 + sc4];
                    nvl = ((const uint4*)g_Al)[srow*208 + (c+1)*8 + sc4];
                }
                if (w < 12){
                    const unsigned* Ah32 = smu + (c&1)*4608;
                    const unsigned* Al32 = Ah32 + 2304;
                    const bool useH = (nt == 2) && (c >= 10);
                    #pragma unroll
                    for (int kl=0; kl<4; kl++){
                        int r0 = (m0+g)*36 + kl*8 + tig;
                        unsigned a0 = Ah32[r0],   a1 = Ah32[r0+288];
                        unsigned a2 = Ah32[r0+4], a3 = Ah32[r0+292];
                        unsigned l0 = Al32[r0],   l1 = Al32[r0+288];
                        unsigned l2 = Al32[r0+4], l3 = Al32[r0+292];
                        if (useH){
                            MMA(aH0,aH1,aH2,aH3, a0,a1,a2,a3, bh[kl].x, bh[kl].y);
                            MMA(aH0,aH1,aH2,aH3, a0,a1,a2,a3, bl[kl].x, bl[kl].y);
                            MMA(aH0,aH1,aH2,aH3, l0,l1,l2,l3, bh[kl].x, bh[kl].y);
                        } else {
                            MMA(aX0,aX1,aX2,aX3, a0,a1,a2,a3, bh[kl].x, bh[kl].y);
                            MMA(aX0,aX1,aX2,aX3, a0,a1,a2,a3, bl[kl].x, bl[kl].y);
                            MMA(aX0,aX1,aX2,aX3, l0,l1,l2,l3, bh[kl].x, bh[kl].y);
                        }
                    }
                }
                if (c+1 < NCH){
                    unsigned boff = ((c+1)&1)*4608;
                    ((uint4*)(smu + boff))[srow*9 + sc4] = nvh;
                    ((uint4*)(smu + boff + 2304))[srow*9 + sc4] = nvl;
                    if (w < 12){
                        size_t wb = ((((size_t)blk*NKT + (c+1)*4)*3 + nt)*2)*32 + lane;
                        #pragma unroll
                        for (int kl=0; kl<4; kl++){
                            bh[kl] = g_Wf[wb + (size_t)kl*192];
                            bl[kl] = g_Wf[wb + (size_t)kl*192 + 32];
                        }
                    }
                }
                __syncthreads();
            }
            // gate frags -> smem planes [4][64][8]
            float* sg = sm;
            if (w < 12){
                float* pl = sg + nt*512;
                int rr = (m0+g)*8 + 2*tig;
                pl[rr]=aX0; pl[rr+1]=aX1; pl[rr+64]=aX2; pl[rr+65]=aX3;
                if (nt == 2){
                    float* p3 = sg + 3*512;
                    p3[rr]=aH0; p3[rr+1]=aH1; p3[rr+64]=aH2; p3[rr+65]=aH3;
                }
            }
            float* Wds = sm + 2048; float* hs = sm + 4096;
            {
                const int row = tid >> 6, c4 = (tid & 63)*4;
                *(float4*)(Wds + row*256 + c4) = *(const float4*)(Wd + (size_t)(blk*8+row)*AA + c4);
            }
            __syncthreads();
            // GRU pointwise
            {
                const int b = tid >> 3, dl = tid & 7, d = blk*8 + dl;
                float gr  = sg[b*8+dl]        + bih[d] + bhh[d];
                float gz  = sg[512 + b*8+dl]  + bih[DD+d] + bhh[DD+d];
                float gin = sg[1024 + b*8+dl] + bih[2*DD+d];
                float ghn = sg[1536 + b*8+dl] + bhh[2*DD+d];
                float r = fsig(gr), z = fsig(gz);
                float n = ftanh(gin + r*ghn);
                float h = g_h[b*DD + d];
                float hn = (1.f - z)*n + z*h;
                g_h[b*DD + d] = hn;
                g_Hb[((size_t)t*BB + b)*DD + d] = hn;
                __nv_bfloat16 hb = __float2bfloat16(hn);
                g_Ah[b*KTOT + PP+EE + d] = hb;
                g_Al[b*KTOT + PP+EE + d] = __float2bfloat16(hn - __bfloat162float(hb));
                hs[b*8 + dl] = hn;
            }
            __syncthreads();
            // dp k-partials for next step (this block's 8 d's)
            {
                const int bg = tid >> 5, ag = tid & 31;
                const int b4 = bg*4, a8 = ag*8;
                float acc[4][8] = {};
                #pragma unroll
                for (int kk = 0; kk < 8; kk++){
                    const float4 w0 = *(const float4*)(Wds + kk*256 + a8);
                    const float4 w1 = *(const float4*)(Wds + kk*256 + a8 + 4);
                    #pragma unroll
                    for (int i = 0; i < 4; i++){
                        const float h = hs[(b4+i)*8 + kk];
                        acc[i][0]+=h*w0.x; acc[i][1]+=h*w0.y; acc[i][2]+=h*w0.z; acc[i][3]+=h*w0.w;
                        acc[i][4]+=h*w1.x; acc[i][5]+=h*w1.y; acc[i][6]+=h*w1.z; acc[i][7]+=h*w1.w;
                    }
                }
                #pragma unroll
                for (int i = 0; i < 4; i++){
                    float* o = g_dpp + ((size_t)blk*BB + b4 + i)*AA + a8;
                    *(float4*)(o)   = make_float4(acc[i][0],acc[i][1],acc[i][2],acc[i][3]);
                    *(float4*)(o+4) = make_float4(acc[i][4],acc[i][5],acc[i][6],acc[i][7]);
                }
            }
        }
        gsync();
    }
}

// ---------------- host ----------------
extern "C" void kernel_launch(void* const* d_in, const int* in_sizes, int n_in,
                              void* d_out, int out_size){
    const float* enc = (const float*)d_in[0];
    const float* tm  = (const float*)d_in[1];
    const float* We  = (const float*)d_in[2];
    const float* be  = (const float*)d_in[3];
    const float* Wd  = (const float*)d_in[4];
    const float* bd  = (const float*)d_in[5];
    const float* v   = (const float*)d_in[6];
    const float* bv  = (const float*)d_in[7];
    const float* W1  = (const float*)d_in[8];
    const float* b1  = (const float*)d_in[9];
    const float* W2  = (const float*)d_in[10];
    const float* b2  = (const float*)d_in[11];
    const float* Wih = (const float*)d_in[12];
    const float* bih = (const float*)d_in[13];
    const float* Whh = (const float*)d_in[14];
    const float* bhh = (const float*)d_in[15];
    const float* Wo  = (const float*)d_in[16];
    const float* bo  = (const float*)d_in[17];
    const float* Ws  = (const float*)d_in[18];
    const float* bs  = (const float*)d_in[19];
    float* out = (float*)d_out;

    float *p_ep, *p_prev, *p_ph, *p_pre, *p_Hb, *p_Cb;
    cudaGetSymbolAddress((void**)&p_ep,   g_ep);
    cudaGetSymbolAddress((void**)&p_prev, g_prev);
    cudaGetSymbolAddress((void**)&p_ph,   g_ph);
    cudaGetSymbolAddress((void**)&p_pre,  g_pre);
    cudaGetSymbolAddress((void**)&p_Hb,   g_Hb);
    cudaGetSymbolAddress((void**)&p_Cb,   g_Cb);

    // precompute
    k_init<<<(NB*BB*AA + 255)/256, 256>>>();
    k_prev<<<(TT*BB*MM + 255)/256, 256>>>(tm);
    k_pack<<<(NB*NKT*3*32 + 255)/256, 256>>>(Wih, Whh);
    sgemm<<<dim3(HP/64, (TT*BB)/64), 256>>>(p_prev, W1, b1, p_ph,  TT*BB, HP, MM, 1, 0, 0);
    sgemm<<<dim3(PP/64, (TT*BB)/64), 256>>>(p_ph,   W2, b2, p_pre, TT*BB, PP, HP, 1, 0, 0);
    sgemm<<<dim3(AA/64, (BB*SS)/64), 256>>>(enc,    We, be, p_ep,  BB*SS, AA, EE, 0, 0, 0);

    // sequential decode: one persistent kernel
    decode<<<NB, TPB>>>(enc, Wd, bd, v, bv, bih, bhh, out);

    // output heads
    sgemm<<<dim3(MM/64, (TT*BB)/64), 256>>>(p_Hb, Wo,           bo,      out, TT*BB, MM, DD, 0, BB, TT);
    sgemm<<<dim3(MM/64, (TT*BB)/64), 256>>>(p_Cb, Wo + DD*MM,   nullptr, out, TT*BB, MM, EE, 2, BB, TT);
    k_stop<<<(TT*BB)/8, 256>>>(Ws, bs, out);
}

// round 5
// speedup vs baseline: 2.1042x; 1.9455x over previous
#include <cuda_runtime.h>
#include <cuda_bf16.h>
#include <cuda_fp16.h>

#define BB 64
#define SS 512
#define EE 512
#define AA 256
#define HP 256
#define PP 128
#define DD 1024
#define MM 128
#define TT 800
#define G3 3072
#define NB 128
#define TPB 512
#define KTOT 1664
#define KT2 2688          /* PP+EE + 2*DD (parity-double h section) */
#define NKT 104
#define NCH 26

// ---------------- static scratch ----------------
__device__ __align__(128) __half g_epH[BB*SS*AA];            // 16.8MB fp16 enc_proj
__device__ __align__(128) __half g_encH[BB*SS*EE];           // 33.5MB fp16 encoder copy
__device__ __align__(128) float g_prev[TT*BB*MM];
__device__ __align__(128) float g_ph  [TT*BB*HP];
__device__ __align__(128) float g_pre [TT*BB*PP];
__device__ __align__(128) float g_h   [BB*DD];
__device__ __align__(128) float g_sc  [BB*SS];
__device__ __align__(128) float g_dpp [BB*NB*AA];            // [b][kpart][a]
__device__ __align__(128) __nv_bfloat16 g_Ah[BB*KT2];
__device__ __align__(128) __nv_bfloat16 g_Al[BB*KT2];
__device__ __align__(128) uint2 g_Wf[(size_t)NB*NKT*3*2*32];
__device__ __align__(128) float g_Hb  [(size_t)TT*BB*DD];
__device__ __align__(128) float g_Cb  [(size_t)TT*BB*EE];
__device__ unsigned g_cnt, g_gen;

__device__ __forceinline__ float fsig(float x){
    float e = __expf(-x);
    return __fdividef(1.f, 1.f + e);
}
__device__ __forceinline__ float ftanh(float x){
    x = fminf(fmaxf(x, -15.f), 15.f);
    float e = __expf(2.f*x);
    return __fdividef(e - 1.f, e + 1.f);
}
__device__ __forceinline__ float tanh_mufu(float x){
    float y; asm("tanh.approx.f32 %0, %1;" : "=f"(y) : "f"(x)); return y;
}

__device__ __forceinline__ void gsync(){
    __syncthreads();
    if (threadIdx.x == 0){
        unsigned gen = *((volatile unsigned*)&g_gen);
        __threadfence();
        if (atomicAdd(&g_cnt, 1u) == NB - 1u){
            atomicExch(&g_cnt, 0u);
            __threadfence();
            atomicAdd(&g_gen, 1u);
        } else {
            while (*((volatile unsigned*)&g_gen) == gen) __nanosleep(64);
        }
        __threadfence();
    }
    __syncthreads();
}

#define MMA(D0,D1,D2,D3,A0,A1,A2,A3,B0,B1) \
    asm volatile("mma.sync.aligned.m16n8k16.row.col.f32.bf16.bf16.f32 " \
        "{%0,%1,%2,%3},{%4,%5,%6,%7},{%8,%9},{%0,%1,%2,%3};" \
        : "+f"(D0),"+f"(D1),"+f"(D2),"+f"(D3) \
        : "r"(A0),"r"(A1),"r"(A2),"r"(A3),"r"(B0),"r"(B1))

// ---------------- generic tiled SGEMM (pre/epilogue only) ----------------
#define BKK 16
__global__ void sgemm(const float* __restrict__ A, const float* __restrict__ B,
                      const float* __restrict__ bias, float* __restrict__ C,
                      int M, int N, int K, int flags, int Bdim, int Tdim)
{
    __shared__ float As[BKK][64];
    __shared__ float Bs[BKK][64];
    const int n0 = blockIdx.x * 64;
    const int m0 = blockIdx.y * 64;
    const int tid = threadIdx.x;
    const int tx = tid & 15;
    const int ty = tid >> 4;
    float acc[4][4] = {};
    const int arow  = tid >> 2;
    const int acol4 = (tid & 3) * 4;
    const int brow  = tid >> 4;
    const int bcol4 = (tid & 15) * 4;

    for (int k = 0; k < K; k += BKK) {
        float4 av = *(const float4*)(A + (size_t)(m0 + arow) * K + k + acol4);
        As[acol4+0][arow] = av.x;
        As[acol4+1][arow] = av.y;
        As[acol4+2][arow] = av.z;
        As[acol4+3][arow] = av.w;
        float4 bvv = *(const float4*)(B + (size_t)(k + brow) * N + n0 + bcol4);
        *(float4*)(&Bs[brow][bcol4]) = bvv;
        __syncthreads();
        #pragma unroll
        for (int kk = 0; kk < BKK; kk++) {
            float4 a4 = *(const float4*)(&As[kk][ty*4]);
            float4 b4 = *(const float4*)(&Bs[kk][tx*4]);
            acc[0][0] += a4.x*b4.x; acc[0][1] += a4.x*b4.y; acc[0][2] += a4.x*b4.z; acc[0][3] += a4.x*b4.w;
            acc[1][0] += a4.y*b4.x; acc[1][1] += a4.y*b4.y; acc[1][2] += a4.y*b4.z; acc[1][3] += a4.y*b4.w;
            acc[2][0] += a4.z*b4.x; acc[2][1] += a4.z*b4.y; acc[2][2] += a4.z*b4.z; acc[2][3] += a4.z*b4.w;
            acc[3][0] += a4.w*b4.x; acc[3][1] += a4.w*b4.y; acc[3][2] += a4.w*b4.z; acc[3][3] += a4.w*b4.w;
        }
        __syncthreads();
    }
    #pragma unroll
    for (int i = 0; i < 4; i++) {
        const int m = m0 + ty*4 + i;
        #pragma unroll
        for (int j = 0; j < 4; j++) {
            const int n = n0 + tx*4 + j;
            float val = acc[i][j];
            if (bias) val += bias[n];
            if (flags & 1) val = fmaxf(val, 0.f);
            size_t idx;
            if (Bdim > 0) {
                const int bq = m % Bdim, tq = m / Bdim;
                idx = ((size_t)bq * Tdim + tq) * N + n;
            } else {
                idx = (size_t)m * N + n;
            }
            if (flags & 4)      ((__half*)C)[idx] = __float2half_rn(val);
            else if (flags & 2) C[idx] += val;
            else                C[idx] = val;
        }
    }
}

__global__ void k_init(){
    int i = blockIdx.x*256 + threadIdx.x;
    if (i < BB*NB*AA) g_dpp[i] = 0.f;
    if (i < BB*KT2){ g_Ah[i] = __float2bfloat16(0.f); g_Al[i] = __float2bfloat16(0.f); }
    if (i < BB*DD) g_h[i] = 0.f;
}

__global__ void k_prev(const float* __restrict__ tm){
    int i = blockIdx.x*256 + threadIdx.x;
    if (i >= TT*BB*MM) return;
    int m  = i & (MM-1);
    int tb = i >> 7;
    int b  = tb & (BB-1);
    int t  = tb >> 6;
    g_prev[i] = (t == 0) ? 0.f : tm[((size_t)b*TT + (t-1))*MM + m];
}

__global__ void k_convE(const float* __restrict__ enc){
    int i = blockIdx.x*256 + threadIdx.x;
    if (i < BB*SS*EE) g_encH[i] = __float2half_rn(enc[i]);
}

// pack [Wih; Whh] (K=1664 x N=3072) into mma B-fragment layout, bf16 hi/lo
__global__ void k_pack(const float* __restrict__ Wih, const float* __restrict__ Whh){
    int id = blockIdx.x*256 + threadIdx.x;
    const int TOTW = NB*NKT*3*32;
    if (id >= TOTW) return;
    int lane = id & 31; int r = id >> 5;
    int nt = r % 3; r /= 3;
    int kt = r % NKT; int blk = r / NKT;
    int g = lane >> 2, tig = lane & 3;
    int n = nt*DD + blk*8 + g;
    int k0 = kt*16;
    int kk[4] = {k0+2*tig, k0+2*tig+1, k0+8+2*tig, k0+9+2*tig};
    unsigned hh[4], ll[4];
    #pragma unroll
    for (int i=0;i<4;i++){
        int k = kk[i];
        float w = (k < PP+EE) ? Wih[(size_t)k*G3 + n] : Whh[(size_t)(k-(PP+EE))*G3 + n];
        __nv_bfloat16 hb = __float2bfloat16(w);
        __nv_bfloat16 lb = __float2bfloat16(w - __bfloat162float(hb));
        hh[i] = *(unsigned short*)&hb;
        ll[i] = *(unsigned short*)&lb;
    }
    size_t base = ((((size_t)blk*NKT + kt)*3 + nt)*2)*32 + lane;
    g_Wf[base]      = make_uint2((hh[1]<<16)|hh[0], (hh[3]<<16)|hh[2]);
    g_Wf[base + 32] = make_uint2((ll[1]<<16)|ll[0], (ll[3]<<16)|ll[2]);
}

__global__ void k_stop(const float* __restrict__ Ws, const float* __restrict__ bs,
                       float* __restrict__ dout){
    const int w = (blockIdx.x*blockDim.x + threadIdx.x) >> 5;
    const int lane = threadIdx.x & 31;
    if (w >= TT*BB) return;
    const float* hrow = g_Hb + (size_t)w*DD;
    const float* crow = g_Cb + (size_t)w*EE;
    float acc = 0.f;
    for (int k = lane; k < DD; k += 32) acc += hrow[k]*Ws[k];
    for (int k = lane; k < EE; k += 32) acc += crow[k]*Ws[DD+k];
    #pragma unroll
    for (int o = 16; o > 0; o >>= 1) acc += __shfl_down_sync(0xffffffffu, acc, o);
    if (lane == 0){
        const int tq = w / BB, bq = w % BB;
        dout[(size_t)BB*TT*MM + (size_t)bq*TT + tq] = acc + bs[0];
    }
}

// one phase-C chunk iteration: MMAs on current buffers, prefetch next into other buffers
#define CITER(c, BHc, BLc, BHn, BLn) { \
    const int cn = (c) + 1; \
    uint4 nvh, nvl; \
    if (cn < NCH){ \
        const int idx4 = (cn < 10) ? cn*8 : 80 + (cn-10)*8 + par*128; \
        nvh = ((const uint4*)g_Ah)[srow*336 + idx4 + sc4]; \
        nvl = ((const uint4*)g_Al)[srow*336 + idx4 + sc4]; \
        if (w < 12){ \
            size_t wb = ((((size_t)blk*NKT + cn*4)*3 + nt)*2)*32 + lane; \
            _Pragma("unroll") \
            for (int kl=0; kl<4; kl++){ \
                BHn[kl] = g_Wf[wb + (size_t)kl*192]; \
                BLn[kl] = g_Wf[wb + (size_t)kl*192 + 32]; \
            } \
        } \
    } \
    if (w < 12){ \
        const unsigned* Ah32 = smu + ((c)&1)*4608; \
        const unsigned* Al32 = Ah32 + 2304; \
        const bool useH = (nt == 2) && ((c) >= 10); \
        _Pragma("unroll") \
        for (int kl=0; kl<4; kl++){ \
            int r0 = (m0+g)*36 + kl*8 + tig; \
            unsigned a0 = Ah32[r0],   a1 = Ah32[r0+288]; \
            unsigned a2 = Ah32[r0+4], a3 = Ah32[r0+292]; \
            unsigned l0 = Al32[r0],   l1 = Al32[r0+288]; \
            unsigned l2 = Al32[r0+4], l3 = Al32[r0+292]; \
            if (useH){ \
                MMA(aH0,aH1,aH2,aH3, a0,a1,a2,a3, BHc[kl].x, BHc[kl].y); \
                MMA(aH0,aH1,aH2,aH3, a0,a1,a2,a3, BLc[kl].x, BLc[kl].y); \
                MMA(aH0,aH1,aH2,aH3, l0,l1,l2,l3, BHc[kl].x, BHc[kl].y); \
            } else { \
                MMA(aX0,aX1,aX2,aX3, a0,a1,a2,a3, BHc[kl].x, BHc[kl].y); \
                MMA(aX0,aX1,aX2,aX3, a0,a1,a2,a3, BLc[kl].x, BLc[kl].y); \
                MMA(aX0,aX1,aX2,aX3, l0,l1,l2,l3, BHc[kl].x, BHc[kl].y); \
            } \
        } \
    } \
    if (cn < NCH){ \
        unsigned boff = (cn&1)*4608; \
        ((uint4*)(smu + boff))[srow*9 + sc4] = nvh; \
        ((uint4*)(smu + boff + 2304))[srow*9 + sc4] = nvl; \
    } \
    __syncthreads(); \
}

// ================= persistent decode kernel =================
__global__ void __launch_bounds__(TPB)
decode(const float* __restrict__ Wd,  const float* __restrict__ bd,
       const float* __restrict__ v,   const float* __restrict__ bv,
       const float* __restrict__ bih, const float* __restrict__ bhh,
       float* __restrict__ out)
{
    __shared__ float sm[9216];
    const int blk = blockIdx.x, tid = threadIdx.x;
    const int lane = tid & 31, wq = tid >> 5;

    for (int t = 0; t < TT; t++){
        const int par = t & 1;
        // ---------- A: dp partial-sum + attention scores ----------
        {
            const int b = blk >> 1, sh = blk & 1;
            float* dps = sm; float* vs = sm + 256; float* part = sm + 512;
            {
                const int a = tid & 255, jh = tid >> 8;
                const float* pp = g_dpp + ((size_t)b*NB + jh*64)*AA + a;
                float s = 0.f;
                #pragma unroll 16
                for (int j = 0; j < 64; j++) s += pp[(size_t)j*AA];
                part[tid] = s;
            }
            if (sh == 0 && tid >= 384){
                int m = tid - 384;
                float pv = g_pre[((size_t)t*BB + b)*PP + m];
                __nv_bfloat16 hb = __float2bfloat16(pv);
                g_Ah[b*KT2 + m] = hb;
                g_Al[b*KT2 + m] = __float2bfloat16(pv - __bfloat162float(hb));
            }
            __syncthreads();
            if (tid < 256){ dps[tid] = part[tid] + part[256+tid] + bd[tid]; vs[tid] = v[tid]; }
            __syncthreads();
            const int sl = tid >> 1, ah = tid & 1;
            const int s = sh*256 + sl;
            const uint4* ep4 = (const uint4*)(g_epH + ((size_t)(b*SS + s))*AA + ah*128);
            const float* dp2 = dps + ah*128;
            const float* v2  = vs  + ah*128;
            float acc = 0.f;
            #pragma unroll 4
            for (int q = 0; q < 16; q++){
                uint4 u = ep4[q];
                float2 f0 = __half22float2(*(__half2*)&u.x);
                float2 f1 = __half22float2(*(__half2*)&u.y);
                float2 f2 = __half22float2(*(__half2*)&u.z);
                float2 f3 = __half22float2(*(__half2*)&u.w);
                const int i0 = q*8;
                acc += v2[i0+0]*tanh_mufu(f0.x + dp2[i0+0]);
                acc += v2[i0+1]*tanh_mufu(f0.y + dp2[i0+1]);
                acc += v2[i0+2]*tanh_mufu(f1.x + dp2[i0+2]);
                acc += v2[i0+3]*tanh_mufu(f1.y + dp2[i0+3]);
                acc += v2[i0+4]*tanh_mufu(f2.x + dp2[i0+4]);
                acc += v2[i0+5]*tanh_mufu(f2.y + dp2[i0+5]);
                acc += v2[i0+6]*tanh_mufu(f3.x + dp2[i0+6]);
                acc += v2[i0+7]*tanh_mufu(f3.y + dp2[i0+7]);
            }
            acc += __shfl_xor_sync(0xffffffffu, acc, 1);
            if (ah == 0) g_sc[b*SS + s] = acc + bv[0];
            __syncthreads();
        }
        gsync();
        // ---------- B: softmax + context ----------
        {
            const int b = blk >> 1, eh = blk & 1;
            float* aw = sm; float* sm2 = sm + 512; float* red = sm + 1536;
            float sc = g_sc[b*SS + tid];
            float mx = sc;
            #pragma unroll
            for (int o = 16; o; o >>= 1) mx = fmaxf(mx, __shfl_xor_sync(0xffffffffu, mx, o));
            if (lane == 0) red[wq] = mx;
            __syncthreads();
            if (tid < 32){
                float mm = (tid < 16) ? red[tid] : -1e30f;
                #pragma unroll
                for (int o = 8; o; o >>= 1) mm = fmaxf(mm, __shfl_xor_sync(0xffffffffu, mm, o));
                if (tid == 0) red[16] = mm;
            }
            __syncthreads();
            mx = red[16];
            float ev = __expf(sc - mx);
            float ss = ev;
            #pragma unroll
            for (int o = 16; o; o >>= 1) ss += __shfl_xor_sync(0xffffffffu, ss, o);
            if (lane == 0) red[wq] = ss;
            __syncthreads();
            if (tid < 32){
                float s2 = (tid < 16) ? red[tid] : 0.f;
                #pragma unroll
                for (int o = 8; o; o >>= 1) s2 += __shfl_xor_sync(0xffffffffu, s2, o);
                if (tid == 0) red[17] = s2;
            }
            __syncthreads();
            const float inv = __fdividef(1.f, red[17]);
            float a = ev * inv;
            aw[tid] = a;
            if (eh == 0)
                out[(size_t)BB*TT*MM + (size_t)BB*TT + ((size_t)b*TT + t)*SS + tid] = a;
            __syncthreads();
            const int el = tid & 127, shalf = tid >> 7;
            const __half2* eb = (const __half2*)(g_encH + ((size_t)(b*SS + shalf*128))*EE + eh*256 + el*2);
            const float* awq = aw + shalf*128;
            float c0 = 0.f, c1 = 0.f;
            #pragma unroll 8
            for (int s2 = 0; s2 < 128; s2++){
                float2 e = __half22float2(eb[(size_t)s2*(EE/2)]);
                float a2 = awq[s2];
                c0 += a2*e.x; c1 += a2*e.y;
            }
            sm2[shalf*256 + el*2]     = c0;
            sm2[shalf*256 + el*2 + 1] = c1;
            __syncthreads();
            if (tid < 256){
                float cc = sm2[tid] + sm2[256+tid] + sm2[512+tid] + sm2[768+tid];
                const int e2 = eh*256 + tid;
                g_Cb[((size_t)t*BB + b)*EE + e2] = cc;
                __nv_bfloat16 hb = __float2bfloat16(cc);
                g_Ah[b*KT2 + PP + e2] = hb;
                g_Al[b*KT2 + PP + e2] = __float2bfloat16(cc - __bfloat162float(hb));
            }
            __syncthreads();
        }
        gsync();
        // ---------- C: gates mma GEMM + GRU + dp partials ----------
        {
            const int w = wq;
            const int g = lane >> 2, tig = lane & 3;
            const int nt = w >> 2;
            const int m0 = (w & 3) * 16;
            float aX0=0,aX1=0,aX2=0,aX3=0, aH0=0,aH1=0,aH2=0,aH3=0;
            uint2 bh0[4], bl0[4], bh1[4], bl1[4];
            const int srow = tid >> 3, sc4 = tid & 7;
            unsigned* smu = (unsigned*)sm;
            {
                uint4 vh = ((const uint4*)g_Ah)[srow*336 + sc4];
                uint4 vl = ((const uint4*)g_Al)[srow*336 + sc4];
                ((uint4*)smu)[srow*9 + sc4] = vh;
                ((uint4*)(smu + 2304))[srow*9 + sc4] = vl;
                if (w < 12){
                    size_t wb = (((size_t)blk*NKT*3 + nt)*2)*32 + lane;
                    #pragma unroll
                    for (int kl=0; kl<4; kl++){
                        bh0[kl] = g_Wf[wb + (size_t)kl*192];
                        bl0[kl] = g_Wf[wb + (size_t)kl*192 + 32];
                    }
                }
            }
            __syncthreads();
            for (int c2 = 0; c2 < NCH; c2 += 2){
                CITER(c2,   bh0, bl0, bh1, bl1)
                CITER(c2+1, bh1, bl1, bh0, bl0)
            }
            // gate frags -> smem planes [4][64][8]
            float* sg = sm;
            if (w < 12){
                float* pl = sg + nt*512;
                int rr = (m0+g)*8 + 2*tig;
                pl[rr]=aX0; pl[rr+1]=aX1; pl[rr+64]=aX2; pl[rr+65]=aX3;
                if (nt == 2){
                    float* p3 = sg + 3*512;
                    p3[rr]=aH0; p3[rr+1]=aH1; p3[rr+64]=aH2; p3[rr+65]=aH3;
                }
            }
            float* Wds = sm + 2048; float* hs = sm + 4096;
            {
                const int row = tid >> 6, c4 = (tid & 63)*4;
                *(float4*)(Wds + row*256 + c4) = *(const float4*)(Wd + (size_t)(blk*8+row)*AA + c4);
            }
            __syncthreads();
            // GRU pointwise
            {
                const int b = tid >> 3, dl = tid & 7, d = blk*8 + dl;
                float gr  = sg[b*8+dl]        + bih[d] + bhh[d];
                float gz  = sg[512 + b*8+dl]  + bih[DD+d] + bhh[DD+d];
                float gin = sg[1024 + b*8+dl] + bih[2*DD+d];
                float ghn = sg[1536 + b*8+dl] + bhh[2*DD+d];
                float r = fsig(gr), z = fsig(gz);
                float n = ftanh(gin + r*ghn);
                float h = g_h[b*DD + d];
                float hn = (1.f - z)*n + z*h;
                g_h[b*DD + d] = hn;
                g_Hb[((size_t)t*BB + b)*DD + d] = hn;
                __nv_bfloat16 hb = __float2bfloat16(hn);
                const int hoff = PP+EE + ((t+1)&1)*DD + d;
                g_Ah[b*KT2 + hoff] = hb;
                g_Al[b*KT2 + hoff] = __float2bfloat16(hn - __bfloat162float(hb));
                hs[b*8 + dl] = hn;
            }
            __syncthreads();
            // dp k-partials for next step (this block's 8 d's), [b][blk][a] layout
            {
                const int bg = tid >> 5, ag = tid & 31;
                const int b4 = bg*4, a8 = ag*8;
                float acc[4][8] = {};
                #pragma unroll
                for (int kk = 0; kk < 8; kk++){
                    const float4 w0 = *(const float4*)(Wds + kk*256 + a8);
                    const float4 w1 = *(const float4*)(Wds + kk*256 + a8 + 4);
                    #pragma unroll
                    for (int i = 0; i < 4; i++){
                        const float h = hs[(b4+i)*8 + kk];
                        acc[i][0]+=h*w0.x; acc[i][1]+=h*w0.y; acc[i][2]+=h*w0.z; acc[i][3]+=h*w0.w;
                        acc[i][4]+=h*w1.x; acc[i][5]+=h*w1.y; acc[i][6]+=h*w1.z; acc[i][7]+=h*w1.w;
                    }
                }
                #pragma unroll
                for (int i = 0; i < 4; i++){
                    float* o = g_dpp + ((size_t)(b4+i)*NB + blk)*AA + a8;
                    *(float4*)(o)   = make_float4(acc[i][0],acc[i][1],acc[i][2],acc[i][3]);
                    *(float4*)(o+4) = make_float4(acc[i][4],acc[i][5],acc[i][6],acc[i][7]);
                }
            }
        }
        gsync();
    }
}

// ---------------- host ----------------
extern "C" void kernel_launch(void* const* d_in, const int* in_sizes, int n_in,
                              void* d_out, int out_size){
    const float* enc = (const float*)d_in[0];
    const float* tm  = (const float*)d_in[1];
    const float* We  = (const float*)d_in[2];
    const float* be  = (const float*)d_in[3];
    const float* Wd  = (const float*)d_in[4];
    const float* bd  = (const float*)d_in[5];
    const float* v   = (const float*)d_in[6];
    const float* bv  = (const float*)d_in[7];
    const float* W1  = (const float*)d_in[8];
    const float* b1  = (const float*)d_in[9];
    const float* W2  = (const float*)d_in[10];
    const float* b2  = (const float*)d_in[11];
    const float* Wih = (const float*)d_in[12];
    const float* bih = (const float*)d_in[13];
    const float* Whh = (const float*)d_in[14];
    const float* bhh = (const float*)d_in[15];
    const float* Wo  = (const float*)d_in[16];
    const float* bo  = (const float*)d_in[17];
    const float* Ws  = (const float*)d_in[18];
    const float* bs  = (const float*)d_in[19];
    float* out = (float*)d_out;

    float *p_prev, *p_ph, *p_pre, *p_Hb, *p_Cb; __half *p_epH;
    cudaGetSymbolAddress((void**)&p_epH,  g_epH);
    cudaGetSymbolAddress((void**)&p_prev, g_prev);
    cudaGetSymbolAddress((void**)&p_ph,   g_ph);
    cudaGetSymbolAddress((void**)&p_pre,  g_pre);
    cudaGetSymbolAddress((void**)&p_Hb,   g_Hb);
    cudaGetSymbolAddress((void**)&p_Cb,   g_Cb);

    // precompute
    k_init<<<(BB*NB*AA + 255)/256, 256>>>();
    k_prev<<<(TT*BB*MM + 255)/256, 256>>>(tm);
    k_convE<<<(BB*SS*EE + 255)/256, 256>>>(enc);
    k_pack<<<(NB*NKT*3*32 + 255)/256, 256>>>(Wih, Whh);
    sgemm<<<dim3(HP/64, (TT*BB)/64), 256>>>(p_prev, W1, b1, p_ph,  TT*BB, HP, MM, 1, 0, 0);
    sgemm<<<dim3(PP/64, (TT*BB)/64), 256>>>(p_ph,   W2, b2, p_pre, TT*BB, PP, HP, 1, 0, 0);
    sgemm<<<dim3(AA/64, (BB*SS)/64), 256>>>(enc,    We, be, (float*)p_epH, BB*SS, AA, EE, 4, 0, 0);

    // sequential decode: one persistent kernel
    decode<<<NB, TPB>>>(Wd, bd, v, bv, bih, bhh, out);

    // output heads
    sgemm<<<dim3(MM/64, (TT*BB)/64), 256>>>(p_Hb, Wo,           bo,      out, TT*BB, MM, DD, 0, BB, TT);
    sgemm<<<dim3(MM/64, (TT*BB)/64), 256>>>(p_Cb, Wo + DD*MM,   nullptr, out, TT*BB, MM, EE, 2, BB, TT);
    k_stop<<<(TT*BB)/8, 256>>>(Ws, bs, out);
}